// round 12
// baseline (speedup 1.0000x reference)
#include <cuda_runtime.h>
#include <cuda_fp16.h>
#include <cuda_bf16.h>
#include <cstdint>

#define BB 64
#define TT 2048
#define DD 512
#define UU 512

// ---------------- device scratch (no cudaMalloc allowed) ----------------
__device__ float g_hb[BB * UU];                 // h_proj + W1_b
__device__ float g_lpart[2][BB * TT];           // logits partials per u-slice
__device__ float g_part[BB][32][2][DD];         // context partials
__device__ __half g_W1f[UU * DD];               // W1^T fp16  [u][k]

// ---------------- helpers ----------------
__device__ __forceinline__ uint32_t smem_u32(const void* p) {
    uint32_t a;
    asm("{ .reg .u64 t; cvta.to.shared.u64 t, %1; cvt.u32.u64 %0, t; }" : "=r"(a) : "l"(p));
    return a;
}
__device__ __forceinline__ float tanh_fast(float x) {
    float y; asm("tanh.approx.f32 %0, %1;" : "=f"(y) : "f"(x)); return y;
}
__device__ __forceinline__ void cp16(uint32_t dst, const void* src) {
    asm volatile("cp.async.cg.shared.global [%0], [%1], 16;" :: "r"(dst), "l"(src) : "memory");
}
__device__ __forceinline__ void ldsm4(uint32_t* r, uint32_t addr) {
    asm volatile("ldmatrix.sync.aligned.m8n8.x4.shared.b16 {%0,%1,%2,%3}, [%4];"
                 : "=r"(r[0]), "=r"(r[1]), "=r"(r[2]), "=r"(r[3]) : "r"(addr));
}
__device__ __forceinline__ void mma_f16(float* c, const uint32_t* a, const uint32_t* b) {
    asm volatile("mma.sync.aligned.m16n8k16.row.col.f32.f16.f16.f32 "
                 "{%0,%1,%2,%3}, {%4,%5,%6,%7}, {%8,%9}, {%0,%1,%2,%3};"
                 : "+f"(c[0]), "+f"(c[1]), "+f"(c[2]), "+f"(c[3])
                 : "r"(a[0]), "r"(a[1]), "r"(a[2]), "r"(a[3]), "r"(b[0]), "r"(b[1]));
}
__device__ __forceinline__ uint32_t cvt2(float a, float b) {
    __half2 h = __float22half2_rn(make_float2(a, b));   // single F2FP.PACK
    return *(uint32_t*)&h;
}

// ---------------------------------------------------------------------------
// k_prep: blocks 0..511  -> W1 [k][u] -> W1^T fp16 [u][k]
//         blocks 512..575 -> hproj: g_hb[b,u] = hidden@W2 + W2_b + W1_b
// ---------------------------------------------------------------------------
__global__ __launch_bounds__(512) void k_prep(
    const float* __restrict__ W1, const float* __restrict__ hidden,
    const float* __restrict__ W2, const float* __restrict__ W2b,
    const float* __restrict__ W1b)
{
    __shared__ float h[DD];
    if (blockIdx.x < 512) {
        int u = blockIdx.x, k = threadIdx.x;
        g_W1f[(size_t)u * DD + k] = __float2half_rn(W1[(size_t)k * UU + u]);
    } else {
        int b = blockIdx.x - 512, u = threadIdx.x;
        h[u] = hidden[b * DD + u];
        __syncthreads();
        float a0 = 0.f, a1 = 0.f, a2 = 0.f, a3 = 0.f;
        #pragma unroll 4
        for (int k = 0; k < DD; k += 4) {
            a0 = fmaf(h[k + 0], W2[(k + 0) * UU + u], a0);
            a1 = fmaf(h[k + 1], W2[(k + 1) * UU + u], a1);
            a2 = fmaf(h[k + 2], W2[(k + 2) * UU + u], a2);
            a3 = fmaf(h[k + 3], W2[(k + 3) * UU + u], a3);
        }
        g_hb[b * UU + u] = ((a0 + a1) + (a2 + a3)) + W2b[u] + W1b[u];
    }
}

// ---------------------------------------------------------------------------
// k_logits: mma.sync fp16 GEMM, BM=64 x BN=256, 256 thr, 2 CTA/SM.
//   2 u-slices -> halved A-convert redundancy vs BN=128.
// ---------------------------------------------------------------------------
#define OFF_A(s)  ((s) * 25600)
#define OFF_B(s)  ((s) * 25600 + 5120)
#define OFF_GS 51200
#define OFF_VS 52224
#define OFF_RED 53248
#define SMEM_BYTES 57600

__global__ __launch_bounds__(256, 2)
void k_logits(const float* __restrict__ F, const float* __restrict__ V)
{
    extern __shared__ __align__(128) uint8_t smem[];
    const uint32_t sb = smem_u32(smem);
    const int tid = threadIdx.x;
    const int lane = tid & 31, wid = tid >> 5;
    const int warp_m = wid & 1, warp_n = wid >> 1;    // 2 x 4 warps -> 64 x 256
    const int us = blockIdx.x;                         // u-slice fastest (2)
    const int m0 = blockIdx.y * 64;
    const int b  = m0 >> 11;

    float* gs  = (float*)(smem + OFF_GS);
    float* vsm = (float*)(smem + OFF_VS);
    gs[tid]  = g_hb[b * UU + us * 256 + tid];
    vsm[tid] = V[us * 256 + tid];

    const int arow = tid >> 2, ah = tid & 3;           // A: 64 rows, 4 chunks/row

    auto cpB = [&](int kt, int buf) {                  // B: 256 rows, 1 row/thread
        const __half* s = g_W1f + (size_t)(us * 256 + tid) * DD + kt * 32;
        uint32_t d = sb + OFF_B(buf) + (uint32_t)(tid * 80);
        cp16(d,      s);
        cp16(d + 16, s + 8);
        cp16(d + 32, s + 16);
        cp16(d + 48, s + 24);
    };
    auto ldA = [&](int kt, float4* fr) {
        const float4* p = (const float4*)(F + (size_t)(m0 + arow) * DD + kt * 32 + ah * 8);
        fr[0] = p[0]; fr[1] = p[1];
    };
    auto stA = [&](const float4* fr, int buf) {
        uint32_t hw0 = cvt2(fr[0].x, fr[0].y);
        uint32_t hw1 = cvt2(fr[0].z, fr[0].w);
        uint32_t hw2 = cvt2(fr[1].x, fr[1].y);
        uint32_t hw3 = cvt2(fr[1].z, fr[1].w);
        *(uint4*)(smem + OFF_A(buf) + arow * 80 + ah * 16) = make_uint4(hw0, hw1, hw2, hw3);
    };

    float acc[2][8][4];
    #pragma unroll
    for (int i = 0; i < 2; i++)
        #pragma unroll
        for (int j = 0; j < 8; j++)
            #pragma unroll
            for (int q = 0; q < 4; q++) acc[i][j][q] = 0.f;

    float4 fr[2];
    cpB(0, 0); asm volatile("cp.async.commit_group;" ::: "memory");
    cpB(1, 1); asm volatile("cp.async.commit_group;" ::: "memory");
    ldA(0, fr); stA(fr, 0);
    ldA(1, fr);
    asm volatile("cp.async.wait_group 1;" ::: "memory");
    __syncthreads();

    #pragma unroll 1
    for (int t = 0; t < 16; t++) {
        const int buf = t & 1;
        const uint32_t ab = sb + OFF_A(buf);
        const uint32_t bb = sb + OFF_B(buf);
        #pragma unroll
        for (int ks = 0; ks < 2; ks++) {
            const uint32_t kb = ks * 32;
            uint32_t Ah[2][4], Bv[4][4];
            #pragma unroll
            for (int mt = 0; mt < 2; mt++) {
                uint32_t ro = (uint32_t)(warp_m * 32 + mt * 16 + (lane & 15)) * 80 + kb + ((lane >> 4) << 4);
                ldsm4(Ah[mt], ab + ro);
            }
            #pragma unroll
            for (int p = 0; p < 4; p++) {
                uint32_t bo = (uint32_t)(warp_n * 64 + p * 16 + ((lane >> 4) << 3) + (lane & 7)) * 80
                              + kb + (((lane >> 3) & 1) << 4);
                ldsm4(Bv[p], bb + bo);
            }
            #pragma unroll
            for (int mt = 0; mt < 2; mt++)
                #pragma unroll
                for (int p = 0; p < 4; p++) {
                    mma_f16(acc[mt][2 * p],     Ah[mt], &Bv[p][0]);
                    mma_f16(acc[mt][2 * p + 1], Ah[mt], &Bv[p][2]);
                }
        }
        if (t == 15) break;
        __syncthreads();
        stA(fr, (t + 1) & 1);
        if (t + 2 < 16) {
            ldA(t + 2, fr);
            cpB(t + 2, buf);
            asm volatile("cp.async.commit_group;" ::: "memory");
            asm volatile("cp.async.wait_group 1;" ::: "memory");
        } else {
            asm volatile("cp.async.wait_group 0;" ::: "memory");
        }
        __syncthreads();
    }

    // epilogue: partial logits over this u-slice (256 cols)
    float* red = (float*)(smem + OFF_RED);
    #pragma unroll
    for (int mt = 0; mt < 2; mt++)
        #pragma unroll
        for (int hf = 0; hf < 2; hf++) {
            float p = 0.f;
            #pragma unroll
            for (int nt = 0; nt < 8; nt++) {
                int u = warp_n * 64 + nt * 8 + (lane & 3) * 2;
                p += tanh_fast(acc[mt][nt][hf * 2 + 0] + gs[u])     * vsm[u];
                p += tanh_fast(acc[mt][nt][hf * 2 + 1] + gs[u + 1]) * vsm[u + 1];
            }
            int ml = warp_m * 32 + mt * 16 + hf * 8 + (lane >> 2);
            red[ml * 17 + warp_n * 4 + (lane & 3)] = p;
        }
    __syncthreads();
    if (tid < 64) {
        float s = 0.f;
        #pragma unroll
        for (int i = 0; i < 16; i++) s += red[tid * 17 + i];
        g_lpart[us][m0 + tid] = s;
    }
}

// ---------------------------------------------------------------------------
// k_softmax: sum u-slice partials, softmax over T
// ---------------------------------------------------------------------------
__global__ __launch_bounds__(256) void k_softmax(float* __restrict__ out_w)
{
    int b = blockIdx.x, tid = threadIdx.x;
    __shared__ float smax[8], ssum[8];
    float v[8];
    float mx = -1e30f;
    #pragma unroll
    for (int i = 0; i < 8; i++) {
        int idx = b * TT + tid + i * 256;
        v[i] = g_lpart[0][idx] + g_lpart[1][idx];
        mx = fmaxf(mx, v[i]);
    }
    #pragma unroll
    for (int o = 16; o > 0; o >>= 1) mx = fmaxf(mx, __shfl_xor_sync(~0u, mx, o));
    if ((tid & 31) == 0) smax[tid >> 5] = mx;
    __syncthreads();
    mx = smax[0];
    #pragma unroll
    for (int i = 1; i < 8; i++) mx = fmaxf(mx, smax[i]);
    float s = 0.f;
    #pragma unroll
    for (int i = 0; i < 8; i++) { v[i] = expf(v[i] - mx); s += v[i]; }
    #pragma unroll
    for (int o = 16; o > 0; o >>= 1) s += __shfl_xor_sync(~0u, s, o);
    if ((tid & 31) == 0) ssum[tid >> 5] = s;
    __syncthreads();
    s = ssum[0];
    #pragma unroll
    for (int i = 1; i < 8; i++) s += ssum[i];
    float inv = 1.f / s;
    #pragma unroll
    for (int i = 0; i < 8; i++) out_w[b * TT + tid + i * 256] = v[i] * inv;
}

// ---------------------------------------------------------------------------
// k_ctx_part / k_ctx_red: context = sum_t w * F, two-stage deterministic
// ---------------------------------------------------------------------------
__global__ __launch_bounds__(256) void k_ctx_part(
    const float* __restrict__ F, const float* __restrict__ w)
{
    int tc = blockIdx.x, b = blockIdx.y, tid = threadIdx.x;
    __shared__ float ws[64];
    if (tid < 64) ws[tid] = w[b * TT + tc * 64 + tid];
    __syncthreads();
    int q = tid & 127, r2 = tid >> 7;
    const float4* F4 = (const float4*)(F + ((size_t)b * TT + (size_t)tc * 64) * DD) + q;
    float ax = 0.f, ay = 0.f, az = 0.f, aw = 0.f;
    #pragma unroll 8
    for (int i = 0; i < 32; i++) {
        int t = r2 + 2 * i;
        float wv = ws[t];
        float4 v = F4[(size_t)t * 128];
        ax = fmaf(wv, v.x, ax); ay = fmaf(wv, v.y, ay);
        az = fmaf(wv, v.z, az); aw = fmaf(wv, v.w, aw);
    }
    float4 o; o.x = ax; o.y = ay; o.z = az; o.w = aw;
    ((float4*)&g_part[b][tc][r2][0])[q] = o;
}

__global__ __launch_bounds__(512) void k_ctx_red(float* __restrict__ out_c)
{
    int b = blockIdx.x, d = threadIdx.x;
    float s = 0.f;
    const float* p = &g_part[b][0][0][0];
    #pragma unroll
    for (int i = 0; i < 64; i++) s += p[i * DD + d];
    out_c[b * DD + d] = s;
}

// ---------------------------------------------------------------------------
extern "C" void kernel_launch(void* const* d_in, const int* in_sizes, int n_in,
                              void* d_out, int out_size)
{
    const float* features = (const float*)d_in[0];
    const float* hidden   = (const float*)d_in[1];
    const float* W1_w     = (const float*)d_in[2];
    const float* W1_b     = (const float*)d_in[3];
    const float* W2_w     = (const float*)d_in[4];
    const float* W2_b     = (const float*)d_in[5];
    const float* V_w      = (const float*)d_in[6];
    // V_b cancels in softmax

    float* out   = (float*)d_out;
    float* out_c = out;               // [B, D]
    float* out_w = out + BB * DD;     // [B, T, 1]

    cudaFuncSetAttribute(k_logits, cudaFuncAttributeMaxDynamicSharedMemorySize, SMEM_BYTES);

    k_prep   <<<576, 512>>>(W1_w, hidden, W2_w, W2_b, W1_b);
    k_logits <<<dim3(2, 2048), 256, SMEM_BYTES>>>(features, V_w);
    k_softmax<<<BB, 256>>>(out_w);
    k_ctx_part<<<dim3(32, BB), 256>>>(features, out_w);
    k_ctx_red<<<BB, 512>>>(out_c);
}

// round 14
// speedup vs baseline: 1.1826x; 1.1826x over previous
#include <cuda_runtime.h>
#include <cuda_fp16.h>
#include <cuda_bf16.h>
#include <cstdint>

#define BB 64
#define TT 2048
#define DD 512
#define UU 512

// ---------------- device scratch (no cudaMalloc allowed) ----------------
__device__ float g_hb[BB * UU];                 // h_proj + W1_b
__device__ float g_lpart[4][BB * TT];           // logits partials per u-slice
__device__ float g_part[BB][32][2][DD];         // context partials
__device__ __half g_W1f[UU * DD];               // W1^T fp16  [u][k]

// ---------------- helpers ----------------
__device__ __forceinline__ uint32_t smem_u32(const void* p) {
    uint32_t a;
    asm("{ .reg .u64 t; cvta.to.shared.u64 t, %1; cvt.u32.u64 %0, t; }" : "=r"(a) : "l"(p));
    return a;
}
__device__ __forceinline__ float tanh_fast(float x) {
    float y; asm("tanh.approx.f32 %0, %1;" : "=f"(y) : "f"(x)); return y;
}
__device__ __forceinline__ void cp16(uint32_t dst, const void* src) {
    asm volatile("cp.async.cg.shared.global [%0], [%1], 16;" :: "r"(dst), "l"(src) : "memory");
}
__device__ __forceinline__ void ldsm4(uint32_t* r, uint32_t addr) {
    asm volatile("ldmatrix.sync.aligned.m8n8.x4.shared.b16 {%0,%1,%2,%3}, [%4];"
                 : "=r"(r[0]), "=r"(r[1]), "=r"(r[2]), "=r"(r[3]) : "r"(addr));
}
__device__ __forceinline__ void mma_f16(float* c, const uint32_t* a, const uint32_t* b) {
    asm volatile("mma.sync.aligned.m16n8k16.row.col.f32.f16.f16.f32 "
                 "{%0,%1,%2,%3}, {%4,%5,%6,%7}, {%8,%9}, {%0,%1,%2,%3};"
                 : "+f"(c[0]), "+f"(c[1]), "+f"(c[2]), "+f"(c[3])
                 : "r"(a[0]), "r"(a[1]), "r"(a[2]), "r"(a[3]), "r"(b[0]), "r"(b[1]));
}
__device__ __forceinline__ uint32_t cvt2(float a, float b) {
    __half2 h = __float22half2_rn(make_float2(a, b));   // single packed convert
    return *(uint32_t*)&h;
}

// ---------------------------------------------------------------------------
// k_prep: blocks 0..511  -> W1 [k][u] -> W1^T fp16 [u][k]
//         blocks 512..575 -> hproj: g_hb[b,u] = hidden@W2 + W2_b + W1_b
// ---------------------------------------------------------------------------
__global__ __launch_bounds__(512) void k_prep(
    const float* __restrict__ W1, const float* __restrict__ hidden,
    const float* __restrict__ W2, const float* __restrict__ W2b,
    const float* __restrict__ W1b)
{
    __shared__ float h[DD];
    if (blockIdx.x < 512) {
        int u = blockIdx.x, k = threadIdx.x;
        g_W1f[(size_t)u * DD + k] = __float2half_rn(W1[(size_t)k * UU + u]);
    } else {
        int b = blockIdx.x - 512, u = threadIdx.x;
        h[u] = hidden[b * DD + u];
        __syncthreads();
        float a0 = 0.f, a1 = 0.f, a2 = 0.f, a3 = 0.f;
        #pragma unroll 4
        for (int k = 0; k < DD; k += 4) {
            a0 = fmaf(h[k + 0], W2[(k + 0) * UU + u], a0);
            a1 = fmaf(h[k + 1], W2[(k + 1) * UU + u], a1);
            a2 = fmaf(h[k + 2], W2[(k + 2) * UU + u], a2);
            a3 = fmaf(h[k + 3], W2[(k + 3) * UU + u], a3);
        }
        g_hb[b * UU + u] = ((a0 + a1) + (a2 + a3)) + W2b[u] + W1b[u];
    }
}

// ---------------------------------------------------------------------------
// k_logits: mma.sync fp16 GEMM (BM=128, BN=128, 2 CTA/SM) — proven 419.8 config,
//   with packed F2FP convert in stA.
// ---------------------------------------------------------------------------
#define OFF_A(b)  ((b) * 20480 + 0)
#define OFF_B(b)  ((b) * 20480 + 10240)
#define OFF_GS 40960
#define OFF_VS 41472
#define OFF_RED 41984
#define SMEM_BYTES 46592

__global__ __launch_bounds__(256, 2)
void k_logits(const float* __restrict__ F, const float* __restrict__ V)
{
    extern __shared__ __align__(128) uint8_t smem[];
    const uint32_t sb = smem_u32(smem);
    const int tid = threadIdx.x;
    const int lane = tid & 31, wid = tid >> 5;
    const int warp_m = wid & 3, warp_n = wid >> 2;
    const int us = blockIdx.x;              // u-slice fastest -> L2 sharing of A
    const int m0 = blockIdx.y * 128;
    const int b  = m0 >> 11;

    float* gs  = (float*)(smem + OFF_GS);
    float* vsm = (float*)(smem + OFF_VS);
    if (tid < 128) {
        gs[tid]  = g_hb[b * UU + us * 128 + tid];
        vsm[tid] = V[us * 128 + tid];
    }

    const int arow = tid >> 1, ah = tid & 1;

    auto cpB = [&](int kt, int buf) {
        const __half* s = g_W1f + (size_t)(us * 128 + arow) * DD + kt * 32 + ah * 16;
        uint32_t d = (uint32_t)(arow * 80 + ah * 32);
        cp16(sb + OFF_B(buf) + d,      s);
        cp16(sb + OFF_B(buf) + d + 16, s + 8);
    };
    auto ldA = [&](int kt, float4* fr) {
        const float4* p = (const float4*)(F + (size_t)(m0 + arow) * DD + kt * 32 + ah * 16);
        fr[0] = p[0]; fr[1] = p[1]; fr[2] = p[2]; fr[3] = p[3];
    };
    auto stA = [&](const float4* fr, int buf) {
        uint32_t hw[8];
        hw[0] = cvt2(fr[0].x, fr[0].y); hw[1] = cvt2(fr[0].z, fr[0].w);
        hw[2] = cvt2(fr[1].x, fr[1].y); hw[3] = cvt2(fr[1].z, fr[1].w);
        hw[4] = cvt2(fr[2].x, fr[2].y); hw[5] = cvt2(fr[2].z, fr[2].w);
        hw[6] = cvt2(fr[3].x, fr[3].y); hw[7] = cvt2(fr[3].z, fr[3].w);
        uint32_t d = (uint32_t)(arow * 80 + ah * 32);
        *(uint4*)(smem + OFF_A(buf) + d)      = make_uint4(hw[0], hw[1], hw[2], hw[3]);
        *(uint4*)(smem + OFF_A(buf) + d + 16) = make_uint4(hw[4], hw[5], hw[6], hw[7]);
    };

    float acc[2][8][4];
    #pragma unroll
    for (int i = 0; i < 2; i++)
        #pragma unroll
        for (int j = 0; j < 8; j++)
            #pragma unroll
            for (int q = 0; q < 4; q++) acc[i][j][q] = 0.f;

    float4 fr[4];
    cpB(0, 0); asm volatile("cp.async.commit_group;" ::: "memory");
    cpB(1, 1); asm volatile("cp.async.commit_group;" ::: "memory");
    ldA(0, fr); stA(fr, 0);
    ldA(1, fr);
    asm volatile("cp.async.wait_group 1;" ::: "memory");
    __syncthreads();

    #pragma unroll 1
    for (int t = 0; t < 16; t++) {
        const int buf = t & 1;
        const uint32_t ab = sb + OFF_A(buf);
        const uint32_t bb = sb + OFF_B(buf);
        #pragma unroll
        for (int ks = 0; ks < 2; ks++) {
            const uint32_t kb = ks * 32;
            uint32_t Ah[2][4], Bv[4][4];
            #pragma unroll
            for (int mt = 0; mt < 2; mt++) {
                uint32_t ro = (uint32_t)(warp_m * 32 + mt * 16 + (lane & 15)) * 80 + kb + ((lane >> 4) << 4);
                ldsm4(Ah[mt], ab + ro);
            }
            #pragma unroll
            for (int p = 0; p < 4; p++) {
                uint32_t bo = (uint32_t)(warp_n * 64 + p * 16 + ((lane >> 4) << 3) + (lane & 7)) * 80
                              + kb + (((lane >> 3) & 1) << 4);
                ldsm4(Bv[p], bb + bo);
            }
            #pragma unroll
            for (int mt = 0; mt < 2; mt++)
                #pragma unroll
                for (int p = 0; p < 4; p++) {
                    mma_f16(acc[mt][2 * p],     Ah[mt], &Bv[p][0]);
                    mma_f16(acc[mt][2 * p + 1], Ah[mt], &Bv[p][2]);
                }
        }
        if (t == 15) break;
        __syncthreads();
        stA(fr, (t + 1) & 1);
        if (t + 2 < 16) {
            ldA(t + 2, fr);
            cpB(t + 2, buf);
            asm volatile("cp.async.commit_group;" ::: "memory");
            asm volatile("cp.async.wait_group 1;" ::: "memory");
        } else {
            asm volatile("cp.async.wait_group 0;" ::: "memory");
        }
        __syncthreads();
    }

    // epilogue: partial logits over this u-slice
    float* red = (float*)(smem + OFF_RED);
    #pragma unroll
    for (int mt = 0; mt < 2; mt++)
        #pragma unroll
        for (int hf = 0; hf < 2; hf++) {
            float p = 0.f;
            #pragma unroll
            for (int nt = 0; nt < 8; nt++) {
                int u = warp_n * 64 + nt * 8 + (lane & 3) * 2;
                p += tanh_fast(acc[mt][nt][hf * 2 + 0] + gs[u])     * vsm[u];
                p += tanh_fast(acc[mt][nt][hf * 2 + 1] + gs[u + 1]) * vsm[u + 1];
            }
            int ml = warp_m * 32 + mt * 16 + hf * 8 + (lane >> 2);
            red[ml * 9 + warp_n * 4 + (lane & 3)] = p;
        }
    __syncthreads();
    if (tid < 128) {
        float s = 0.f;
        #pragma unroll
        for (int i = 0; i < 8; i++) s += red[tid * 9 + i];
        g_lpart[us][m0 + tid] = s;
    }
}

// ---------------------------------------------------------------------------
// k_softmax: sum u-slice partials, softmax over T
// ---------------------------------------------------------------------------
__global__ __launch_bounds__(256) void k_softmax(float* __restrict__ out_w)
{
    int b = blockIdx.x, tid = threadIdx.x;
    __shared__ float smax[8], ssum[8];
    float v[8];
    float mx = -1e30f;
    #pragma unroll
    for (int i = 0; i < 8; i++) {
        int idx = b * TT + tid + i * 256;
        v[i] = g_lpart[0][idx] + g_lpart[1][idx] + g_lpart[2][idx] + g_lpart[3][idx];
        mx = fmaxf(mx, v[i]);
    }
    #pragma unroll
    for (int o = 16; o > 0; o >>= 1) mx = fmaxf(mx, __shfl_xor_sync(~0u, mx, o));
    if ((tid & 31) == 0) smax[tid >> 5] = mx;
    __syncthreads();
    mx = smax[0];
    #pragma unroll
    for (int i = 1; i < 8; i++) mx = fmaxf(mx, smax[i]);
    float s = 0.f;
    #pragma unroll
    for (int i = 0; i < 8; i++) { v[i] = expf(v[i] - mx); s += v[i]; }
    #pragma unroll
    for (int o = 16; o > 0; o >>= 1) s += __shfl_xor_sync(~0u, s, o);
    if ((tid & 31) == 0) ssum[tid >> 5] = s;
    __syncthreads();
    s = ssum[0];
    #pragma unroll
    for (int i = 1; i < 8; i++) s += ssum[i];
    float inv = 1.f / s;
    #pragma unroll
    for (int i = 0; i < 8; i++) out_w[b * TT + tid + i * 256] = v[i] * inv;
}

// ---------------------------------------------------------------------------
// k_ctx_part / k_ctx_red: context = sum_t w * F, two-stage deterministic
// ---------------------------------------------------------------------------
__global__ __launch_bounds__(256) void k_ctx_part(
    const float* __restrict__ F, const float* __restrict__ w)
{
    int tc = blockIdx.x, b = blockIdx.y, tid = threadIdx.x;
    __shared__ float ws[64];
    if (tid < 64) ws[tid] = w[b * TT + tc * 64 + tid];
    __syncthreads();
    int q = tid & 127, r2 = tid >> 7;
    const float4* F4 = (const float4*)(F + ((size_t)b * TT + (size_t)tc * 64) * DD) + q;
    float ax = 0.f, ay = 0.f, az = 0.f, aw = 0.f;
    #pragma unroll 8
    for (int i = 0; i < 32; i++) {
        int t = r2 + 2 * i;
        float wv = ws[t];
        float4 v = F4[(size_t)t * 128];
        ax = fmaf(wv, v.x, ax); ay = fmaf(wv, v.y, ay);
        az = fmaf(wv, v.z, az); aw = fmaf(wv, v.w, aw);
    }
    float4 o; o.x = ax; o.y = ay; o.z = az; o.w = aw;
    ((float4*)&g_part[b][tc][r2][0])[q] = o;
}

__global__ __launch_bounds__(512) void k_ctx_red(float* __restrict__ out_c)
{
    int b = blockIdx.x, d = threadIdx.x;
    float s = 0.f;
    const float* p = &g_part[b][0][0][0];
    #pragma unroll
    for (int i = 0; i < 64; i++) s += p[i * DD + d];
    out_c[b * DD + d] = s;
}

// ---------------------------------------------------------------------------
extern "C" void kernel_launch(void* const* d_in, const int* in_sizes, int n_in,
                              void* d_out, int out_size)
{
    const float* features = (const float*)d_in[0];
    const float* hidden   = (const float*)d_in[1];
    const float* W1_w     = (const float*)d_in[2];
    const float* W1_b     = (const float*)d_in[3];
    const float* W2_w     = (const float*)d_in[4];
    const float* W2_b     = (const float*)d_in[5];
    const float* V_w      = (const float*)d_in[6];
    // V_b cancels in softmax

    float* out   = (float*)d_out;
    float* out_c = out;               // [B, D]
    float* out_w = out + BB * DD;     // [B, T, 1]

    cudaFuncSetAttribute(k_logits, cudaFuncAttributeMaxDynamicSharedMemorySize, SMEM_BYTES);

    k_prep   <<<576, 512>>>(W1_w, hidden, W2_w, W2_b, W1_b);
    k_logits <<<dim3(4, 1024), 256, SMEM_BYTES>>>(features, V_w);
    k_softmax<<<BB, 256>>>(out_w);
    k_ctx_part<<<dim3(32, BB), 256>>>(features, out_w);
    k_ctx_red<<<BB, 512>>>(out_c);
}

// round 16
// speedup vs baseline: 1.2130x; 1.0257x over previous
#include <cuda_runtime.h>
#include <cuda_fp16.h>
#include <cuda_bf16.h>
#include <cstdint>

#define BB 64
#define TT 2048
#define DD 512
#define UU 512

// ---------------- device scratch (no cudaMalloc allowed) ----------------
__device__ float g_hb[BB * UU];                 // h_proj + W1_b
__device__ float g_lpart[4][BB * TT];           // logits partials per u-slice
__device__ float g_part[BB][32][2][DD];         // context partials
__device__ __half g_W1f[UU * DD];               // W1^T fp16  [u][k]

// ---------------- helpers ----------------
__device__ __forceinline__ uint32_t smem_u32(const void* p) {
    uint32_t a;
    asm("{ .reg .u64 t; cvta.to.shared.u64 t, %1; cvt.u32.u64 %0, t; }" : "=r"(a) : "l"(p));
    return a;
}
__device__ __forceinline__ float tanh_fast(float x) {
    float y; asm("tanh.approx.f32 %0, %1;" : "=f"(y) : "f"(x)); return y;
}
__device__ __forceinline__ void cp16(uint32_t dst, const void* src) {
    asm volatile("cp.async.cg.shared.global [%0], [%1], 16;" :: "r"(dst), "l"(src) : "memory");
}
__device__ __forceinline__ void ldsm4(uint32_t* r, uint32_t addr) {
    asm volatile("ldmatrix.sync.aligned.m8n8.x4.shared.b16 {%0,%1,%2,%3}, [%4];"
                 : "=r"(r[0]), "=r"(r[1]), "=r"(r[2]), "=r"(r[3]) : "r"(addr));
}
__device__ __forceinline__ void mma_f16(float* c, const uint32_t* a, const uint32_t* b) {
    asm volatile("mma.sync.aligned.m16n8k16.row.col.f32.f16.f16.f32 "
                 "{%0,%1,%2,%3}, {%4,%5,%6,%7}, {%8,%9}, {%0,%1,%2,%3};"
                 : "+f"(c[0]), "+f"(c[1]), "+f"(c[2]), "+f"(c[3])
                 : "r"(a[0]), "r"(a[1]), "r"(a[2]), "r"(a[3]), "r"(b[0]), "r"(b[1]));
}
__device__ __forceinline__ uint32_t cvt2(float a, float b) {
    __half2 h = __float22half2_rn(make_float2(a, b));   // single packed convert
    return *(uint32_t*)&h;
}

// ---------------------------------------------------------------------------
// k_prep: blocks 0..511  -> W1 [k][u] -> W1^T fp16 [u][k]
//         blocks 512..575 -> hproj: g_hb[b,u] = hidden@W2 + W2_b + W1_b
// ---------------------------------------------------------------------------
__global__ __launch_bounds__(512) void k_prep(
    const float* __restrict__ W1, const float* __restrict__ hidden,
    const float* __restrict__ W2, const float* __restrict__ W2b,
    const float* __restrict__ W1b)
{
    __shared__ float h[DD];
    if (blockIdx.x < 512) {
        int u = blockIdx.x, k = threadIdx.x;
        g_W1f[(size_t)u * DD + k] = __float2half_rn(W1[(size_t)k * UU + u]);
    } else {
        int b = blockIdx.x - 512, u = threadIdx.x;
        h[u] = hidden[b * DD + u];
        __syncthreads();
        float a0 = 0.f, a1 = 0.f, a2 = 0.f, a3 = 0.f;
        #pragma unroll 4
        for (int k = 0; k < DD; k += 4) {
            a0 = fmaf(h[k + 0], W2[(k + 0) * UU + u], a0);
            a1 = fmaf(h[k + 1], W2[(k + 1) * UU + u], a1);
            a2 = fmaf(h[k + 2], W2[(k + 2) * UU + u], a2);
            a3 = fmaf(h[k + 3], W2[(k + 3) * UU + u], a3);
        }
        g_hb[b * UU + u] = ((a0 + a1) + (a2 + a3)) + W2b[u] + W1b[u];
    }
}

// ---------------------------------------------------------------------------
// k_logits: mma.sync fp16 GEMM (BM=128, BN=128, 2 CTA/SM),
//   3-stage pipeline, ONE __syncthreads per k-tile.
// ---------------------------------------------------------------------------
#define OFF_A(s)  ((s) * 20480 + 0)
#define OFF_B(s)  ((s) * 20480 + 10240)
#define OFF_GS 61440
#define OFF_VS 61952
#define OFF_RED 62464
#define SMEM_BYTES 67072

__global__ __launch_bounds__(256, 2)
void k_logits(const float* __restrict__ F, const float* __restrict__ V)
{
    extern __shared__ __align__(128) uint8_t smem[];
    const uint32_t sb = smem_u32(smem);
    const int tid = threadIdx.x;
    const int lane = tid & 31, wid = tid >> 5;
    const int warp_m = wid & 3, warp_n = wid >> 2;
    const int us = blockIdx.x;              // u-slice fastest -> L2 sharing of A
    const int m0 = blockIdx.y * 128;
    const int b  = m0 >> 11;

    float* gs  = (float*)(smem + OFF_GS);
    float* vsm = (float*)(smem + OFF_VS);
    if (tid < 128) {
        gs[tid]  = g_hb[b * UU + us * 128 + tid];
        vsm[tid] = V[us * 128 + tid];
    }

    const int arow = tid >> 1, ah = tid & 1;

    auto cpB = [&](int kt, int s) {
        const __half* p = g_W1f + (size_t)(us * 128 + arow) * DD + kt * 32 + ah * 16;
        uint32_t d = (uint32_t)(arow * 80 + ah * 32);
        cp16(sb + OFF_B(s) + d,      p);
        cp16(sb + OFF_B(s) + d + 16, p + 8);
    };
    auto ldA = [&](int kt, float4* fr) {
        const float4* p = (const float4*)(F + (size_t)(m0 + arow) * DD + kt * 32 + ah * 16);
        fr[0] = p[0]; fr[1] = p[1]; fr[2] = p[2]; fr[3] = p[3];
    };
    auto stA = [&](const float4* fr, int s) {
        uint32_t hw[8];
        hw[0] = cvt2(fr[0].x, fr[0].y); hw[1] = cvt2(fr[0].z, fr[0].w);
        hw[2] = cvt2(fr[1].x, fr[1].y); hw[3] = cvt2(fr[1].z, fr[1].w);
        hw[4] = cvt2(fr[2].x, fr[2].y); hw[5] = cvt2(fr[2].z, fr[2].w);
        hw[6] = cvt2(fr[3].x, fr[3].y); hw[7] = cvt2(fr[3].z, fr[3].w);
        uint32_t d = (uint32_t)(arow * 80 + ah * 32);
        *(uint4*)(smem + OFF_A(s) + d)      = make_uint4(hw[0], hw[1], hw[2], hw[3]);
        *(uint4*)(smem + OFF_A(s) + d + 16) = make_uint4(hw[4], hw[5], hw[6], hw[7]);
    };

    float acc[2][8][4];
    #pragma unroll
    for (int i = 0; i < 2; i++)
        #pragma unroll
        for (int j = 0; j < 8; j++)
            #pragma unroll
            for (int q = 0; q < 4; q++) acc[i][j][q] = 0.f;

    float4 fr[4];
    // Prologue: stage tiles 0,1 fully; prefetch tile 2 into registers.
    cpB(0, 0); asm volatile("cp.async.commit_group;" ::: "memory");
    cpB(1, 1); asm volatile("cp.async.commit_group;" ::: "memory");
    ldA(0, fr); stA(fr, 0);
    ldA(1, fr); stA(fr, 1);
    ldA(2, fr);
    asm volatile("cp.async.wait_group 1;" ::: "memory");   // tile 0 B arrived

    #pragma unroll 1
    for (int t = 0; t < 16; t++) {
        __syncthreads();   // publishes: tile t's cp data + stA; frees slot (t+2)%3
        int s2 = (t + 2) % 3;
        if (t + 2 < 16) {
            stA(fr, s2);                    // tile t+2 -> slot freed at iter t-1
            cpB(t + 2, s2);
            asm volatile("cp.async.commit_group;" ::: "memory");
        }
        if (t + 3 < 16) ldA(t + 3, fr);
        if (t + 2 < 16) { asm volatile("cp.async.wait_group 1;" ::: "memory"); }
        else            { asm volatile("cp.async.wait_group 0;" ::: "memory"); }

        const int s = t % 3;
        const uint32_t ab = sb + OFF_A(s);
        const uint32_t bb = sb + OFF_B(s);
        #pragma unroll
        for (int ks = 0; ks < 2; ks++) {
            const uint32_t kb = ks * 32;
            uint32_t Ah[2][4], Bv[4][4];
            #pragma unroll
            for (int mt = 0; mt < 2; mt++) {
                uint32_t ro = (uint32_t)(warp_m * 32 + mt * 16 + (lane & 15)) * 80 + kb + ((lane >> 4) << 4);
                ldsm4(Ah[mt], ab + ro);
            }
            #pragma unroll
            for (int p = 0; p < 4; p++) {
                uint32_t bo = (uint32_t)(warp_n * 64 + p * 16 + ((lane >> 4) << 3) + (lane & 7)) * 80
                              + kb + (((lane >> 3) & 1) << 4);
                ldsm4(Bv[p], bb + bo);
            }
            #pragma unroll
            for (int mt = 0; mt < 2; mt++)
                #pragma unroll
                for (int p = 0; p < 4; p++) {
                    mma_f16(acc[mt][2 * p],     Ah[mt], &Bv[p][0]);
                    mma_f16(acc[mt][2 * p + 1], Ah[mt], &Bv[p][2]);
                }
        }
    }

    // epilogue: partial logits over this u-slice
    float* red = (float*)(smem + OFF_RED);
    #pragma unroll
    for (int mt = 0; mt < 2; mt++)
        #pragma unroll
        for (int hf = 0; hf < 2; hf++) {
            float p = 0.f;
            #pragma unroll
            for (int nt = 0; nt < 8; nt++) {
                int u = warp_n * 64 + nt * 8 + (lane & 3) * 2;
                p += tanh_fast(acc[mt][nt][hf * 2 + 0] + gs[u])     * vsm[u];
                p += tanh_fast(acc[mt][nt][hf * 2 + 1] + gs[u + 1]) * vsm[u + 1];
            }
            int ml = warp_m * 32 + mt * 16 + hf * 8 + (lane >> 2);
            red[ml * 9 + warp_n * 4 + (lane & 3)] = p;
        }
    __syncthreads();
    if (tid < 128) {
        float s = 0.f;
        #pragma unroll
        for (int i = 0; i < 8; i++) s += red[tid * 9 + i];
        g_lpart[us][m0 + tid] = s;
    }
}

// ---------------------------------------------------------------------------
// k_softmax: sum u-slice partials, softmax over T
// ---------------------------------------------------------------------------
__global__ __launch_bounds__(256) void k_softmax(float* __restrict__ out_w)
{
    int b = blockIdx.x, tid = threadIdx.x;
    __shared__ float smax[8], ssum[8];
    float v[8];
    float mx = -1e30f;
    #pragma unroll
    for (int i = 0; i < 8; i++) {
        int idx = b * TT + tid + i * 256;
        v[i] = g_lpart[0][idx] + g_lpart[1][idx] + g_lpart[2][idx] + g_lpart[3][idx];
        mx = fmaxf(mx, v[i]);
    }
    #pragma unroll
    for (int o = 16; o > 0; o >>= 1) mx = fmaxf(mx, __shfl_xor_sync(~0u, mx, o));
    if ((tid & 31) == 0) smax[tid >> 5] = mx;
    __syncthreads();
    mx = smax[0];
    #pragma unroll
    for (int i = 1; i < 8; i++) mx = fmaxf(mx, smax[i]);
    float s = 0.f;
    #pragma unroll
    for (int i = 0; i < 8; i++) { v[i] = expf(v[i] - mx); s += v[i]; }
    #pragma unroll
    for (int o = 16; o > 0; o >>= 1) s += __shfl_xor_sync(~0u, s, o);
    if ((tid & 31) == 0) ssum[tid >> 5] = s;
    __syncthreads();
    s = ssum[0];
    #pragma unroll
    for (int i = 1; i < 8; i++) s += ssum[i];
    float inv = 1.f / s;
    #pragma unroll
    for (int i = 0; i < 8; i++) out_w[b * TT + tid + i * 256] = v[i] * inv;
}

// ---------------------------------------------------------------------------
// k_ctx_part / k_ctx_red: context = sum_t w * F, two-stage deterministic
// ---------------------------------------------------------------------------
__global__ __launch_bounds__(256) void k_ctx_part(
    const float* __restrict__ F, const float* __restrict__ w)
{
    int tc = blockIdx.x, b = blockIdx.y, tid = threadIdx.x;
    __shared__ float ws[64];
    if (tid < 64) ws[tid] = w[b * TT + tc * 64 + tid];
    __syncthreads();
    int q = tid & 127, r2 = tid >> 7;
    const float4* F4 = (const float4*)(F + ((size_t)b * TT + (size_t)tc * 64) * DD) + q;
    float ax = 0.f, ay = 0.f, az = 0.f, aw = 0.f;
    #pragma unroll 8
    for (int i = 0; i < 32; i++) {
        int t = r2 + 2 * i;
        float wv = ws[t];
        float4 v = F4[(size_t)t * 128];
        ax = fmaf(wv, v.x, ax); ay = fmaf(wv, v.y, ay);
        az = fmaf(wv, v.z, az); aw = fmaf(wv, v.w, aw);
    }
    float4 o; o.x = ax; o.y = ay; o.z = az; o.w = aw;
    ((float4*)&g_part[b][tc][r2][0])[q] = o;
}

__global__ __launch_bounds__(512) void k_ctx_red(float* __restrict__ out_c)
{
    int b = blockIdx.x, d = threadIdx.x;
    float s = 0.f;
    const float* p = &g_part[b][0][0][0];
    #pragma unroll
    for (int i = 0; i < 64; i++) s += p[i * DD + d];
    out_c[b * DD + d] = s;
}

// ---------------------------------------------------------------------------
extern "C" void kernel_launch(void* const* d_in, const int* in_sizes, int n_in,
                              void* d_out, int out_size)
{
    const float* features = (const float*)d_in[0];
    const float* hidden   = (const float*)d_in[1];
    const float* W1_w     = (const float*)d_in[2];
    const float* W1_b     = (const float*)d_in[3];
    const float* W2_w     = (const float*)d_in[4];
    const float* W2_b     = (const float*)d_in[5];
    const float* V_w      = (const float*)d_in[6];
    // V_b cancels in softmax

    float* out   = (float*)d_out;
    float* out_c = out;               // [B, D]
    float* out_w = out + BB * DD;     // [B, T, 1]

    cudaFuncSetAttribute(k_logits, cudaFuncAttributeMaxDynamicSharedMemorySize, SMEM_BYTES);

    k_prep   <<<576, 512>>>(W1_w, hidden, W2_w, W2_b, W1_b);
    k_logits <<<dim3(4, 1024), 256, SMEM_BYTES>>>(features, V_w);
    k_softmax<<<BB, 256>>>(out_w);
    k_ctx_part<<<dim3(32, BB), 256>>>(features, out_w);
    k_ctx_red<<<BB, 512>>>(out_c);
}

// round 17
// speedup vs baseline: 1.2198x; 1.0056x over previous
#include <cuda_runtime.h>
#include <cuda_fp16.h>
#include <cuda_bf16.h>
#include <cstdint>

#define BB 64
#define TT 2048
#define DD 512
#define UU 512

// ---------------- device scratch (no cudaMalloc allowed) ----------------
__device__ float g_hb[BB * UU];                 // h_proj + W1_b
__device__ float g_lpart[4][BB * TT];           // logits partials per u-slice
__device__ float g_part[BB][32][2][DD];         // context partials
__device__ __half g_W1f[UU * DD];               // W1^T fp16  [u][k]

// ---------------- helpers ----------------
__device__ __forceinline__ uint32_t smem_u32(const void* p) {
    uint32_t a;
    asm("{ .reg .u64 t; cvta.to.shared.u64 t, %1; cvt.u32.u64 %0, t; }" : "=r"(a) : "l"(p));
    return a;
}
__device__ __forceinline__ float tanh_fast(float x) {
    float y; asm("tanh.approx.f32 %0, %1;" : "=f"(y) : "f"(x)); return y;
}
__device__ __forceinline__ void cp16(uint32_t dst, const void* src) {
    asm volatile("cp.async.cg.shared.global [%0], [%1], 16;" :: "r"(dst), "l"(src) : "memory");
}
__device__ __forceinline__ void ldsm4(uint32_t* r, uint32_t addr) {
    asm volatile("ldmatrix.sync.aligned.m8n8.x4.shared.b16 {%0,%1,%2,%3}, [%4];"
                 : "=r"(r[0]), "=r"(r[1]), "=r"(r[2]), "=r"(r[3]) : "r"(addr));
}
__device__ __forceinline__ void mma_f16(float* c, const uint32_t* a, const uint32_t* b) {
    asm volatile("mma.sync.aligned.m16n8k16.row.col.f32.f16.f16.f32 "
                 "{%0,%1,%2,%3}, {%4,%5,%6,%7}, {%8,%9}, {%0,%1,%2,%3};"
                 : "+f"(c[0]), "+f"(c[1]), "+f"(c[2]), "+f"(c[3])
                 : "r"(a[0]), "r"(a[1]), "r"(a[2]), "r"(a[3]), "r"(b[0]), "r"(b[1]));
}
__device__ __forceinline__ uint32_t cvt2(float a, float b) {
    __half2 h = __float22half2_rn(make_float2(a, b));   // single packed convert
    return *(uint32_t*)&h;
}

// ---------------------------------------------------------------------------
// k_prep: blocks 0..511  -> W1 [k][u] -> W1^T fp16 [u][k]
//         blocks 512..575 -> hproj: g_hb[b,u] = hidden@W2 + W2_b + W1_b
// ---------------------------------------------------------------------------
__global__ __launch_bounds__(512) void k_prep(
    const float* __restrict__ W1, const float* __restrict__ hidden,
    const float* __restrict__ W2, const float* __restrict__ W2b,
    const float* __restrict__ W1b)
{
    __shared__ float h[DD];
    if (blockIdx.x < 512) {
        int u = blockIdx.x, k = threadIdx.x;
        g_W1f[(size_t)u * DD + k] = __float2half_rn(W1[(size_t)k * UU + u]);
    } else {
        int b = blockIdx.x - 512, u = threadIdx.x;
        h[u] = hidden[b * DD + u];
        __syncthreads();
        float a0 = 0.f, a1 = 0.f, a2 = 0.f, a3 = 0.f;
        #pragma unroll 4
        for (int k = 0; k < DD; k += 4) {
            a0 = fmaf(h[k + 0], W2[(k + 0) * UU + u], a0);
            a1 = fmaf(h[k + 1], W2[(k + 1) * UU + u], a1);
            a2 = fmaf(h[k + 2], W2[(k + 2) * UU + u], a2);
            a3 = fmaf(h[k + 3], W2[(k + 3) * UU + u], a3);
        }
        g_hb[b * UU + u] = ((a0 + a1) + (a2 + a3)) + W2b[u] + W1b[u];
    }
}

// ---------------------------------------------------------------------------
// k_logits: mma.sync fp16 GEMM (BM=128, BN=128, 2 CTA/SM),
//   4-stage pipeline, one __syncthreads per k-tile, relaxed wait_group.
// ---------------------------------------------------------------------------
#define OFF_A(s)  ((s) * 20480 + 0)
#define OFF_B(s)  ((s) * 20480 + 10240)
#define OFF_GS 81920
#define OFF_VS 82432
#define OFF_RED 82944
#define SMEM_BYTES 87552

__global__ __launch_bounds__(256, 2)
void k_logits(const float* __restrict__ F, const float* __restrict__ V)
{
    extern __shared__ __align__(128) uint8_t smem[];
    const uint32_t sb = smem_u32(smem);
    const int tid = threadIdx.x;
    const int lane = tid & 31, wid = tid >> 5;
    const int warp_m = wid & 3, warp_n = wid >> 2;
    const int us = blockIdx.x;              // u-slice fastest -> L2 sharing of A
    const int m0 = blockIdx.y * 128;
    const int b  = m0 >> 11;

    float* gs  = (float*)(smem + OFF_GS);
    float* vsm = (float*)(smem + OFF_VS);
    if (tid < 128) {
        gs[tid]  = g_hb[b * UU + us * 128 + tid];
        vsm[tid] = V[us * 128 + tid];
    }

    const int arow = tid >> 1, ah = tid & 1;

    auto cpB = [&](int kt, int s) {
        const __half* p = g_W1f + (size_t)(us * 128 + arow) * DD + kt * 32 + ah * 16;
        uint32_t d = (uint32_t)(arow * 80 + ah * 32);
        cp16(sb + OFF_B(s) + d,      p);
        cp16(sb + OFF_B(s) + d + 16, p + 8);
    };
    auto ldA = [&](int kt, float4* fr) {
        const float4* p = (const float4*)(F + (size_t)(m0 + arow) * DD + kt * 32 + ah * 16);
        fr[0] = p[0]; fr[1] = p[1]; fr[2] = p[2]; fr[3] = p[3];
    };
    auto stA = [&](const float4* fr, int s) {
        uint32_t hw[8];
        hw[0] = cvt2(fr[0].x, fr[0].y); hw[1] = cvt2(fr[0].z, fr[0].w);
        hw[2] = cvt2(fr[1].x, fr[1].y); hw[3] = cvt2(fr[1].z, fr[1].w);
        hw[4] = cvt2(fr[2].x, fr[2].y); hw[5] = cvt2(fr[2].z, fr[2].w);
        hw[6] = cvt2(fr[3].x, fr[3].y); hw[7] = cvt2(fr[3].z, fr[3].w);
        uint32_t d = (uint32_t)(arow * 80 + ah * 32);
        *(uint4*)(smem + OFF_A(s) + d)      = make_uint4(hw[0], hw[1], hw[2], hw[3]);
        *(uint4*)(smem + OFF_A(s) + d + 16) = make_uint4(hw[4], hw[5], hw[6], hw[7]);
    };

    float acc[2][8][4];
    #pragma unroll
    for (int i = 0; i < 2; i++)
        #pragma unroll
        for (int j = 0; j < 8; j++)
            #pragma unroll
            for (int q = 0; q < 4; q++) acc[i][j][q] = 0.f;

    float4 fr[4];
    // Prologue: stage tiles 0,1,2 fully; prefetch tile 3 into registers.
    cpB(0, 0); asm volatile("cp.async.commit_group;" ::: "memory");
    cpB(1, 1); asm volatile("cp.async.commit_group;" ::: "memory");
    cpB(2, 2); asm volatile("cp.async.commit_group;" ::: "memory");
    ldA(0, fr); stA(fr, 0);
    ldA(1, fr); stA(fr, 1);
    ldA(2, fr); stA(fr, 2);
    ldA(3, fr);
    asm volatile("cp.async.wait_group 2;" ::: "memory");   // tile 0 B arrived

    #pragma unroll 1
    for (int t = 0; t < 16; t++) {
        __syncthreads();   // publishes tile t (cp data + stA); frees slot (t+3)%4
        if (t + 3 < 16) {
            int s3 = (t + 3) & 3;
            stA(fr, s3);                    // tile t+3 -> slot freed at iter t-1
            cpB(t + 3, s3);
            asm volatile("cp.async.commit_group;" ::: "memory");
        }
        if (t + 4 < 16) ldA(t + 4, fr);
        // Guarantee tile t+1 complete by end of this iter (published at t+1's barrier)
        if (t < 13)       { asm volatile("cp.async.wait_group 2;" ::: "memory"); }
        else if (t == 13) { asm volatile("cp.async.wait_group 1;" ::: "memory"); }
        else              { asm volatile("cp.async.wait_group 0;" ::: "memory"); }

        const int s = t & 3;
        const uint32_t ab = sb + OFF_A(s);
        const uint32_t bb = sb + OFF_B(s);
        #pragma unroll
        for (int ks = 0; ks < 2; ks++) {
            const uint32_t kb = ks * 32;
            uint32_t Ah[2][4], Bv[4][4];
            #pragma unroll
            for (int mt = 0; mt < 2; mt++) {
                uint32_t ro = (uint32_t)(warp_m * 32 + mt * 16 + (lane & 15)) * 80 + kb + ((lane >> 4) << 4);
                ldsm4(Ah[mt], ab + ro);
            }
            #pragma unroll
            for (int p = 0; p < 4; p++) {
                uint32_t bo = (uint32_t)(warp_n * 64 + p * 16 + ((lane >> 4) << 3) + (lane & 7)) * 80
                              + kb + (((lane >> 3) & 1) << 4);
                ldsm4(Bv[p], bb + bo);
            }
            #pragma unroll
            for (int mt = 0; mt < 2; mt++)
                #pragma unroll
                for (int p = 0; p < 4; p++) {
                    mma_f16(acc[mt][2 * p],     Ah[mt], &Bv[p][0]);
                    mma_f16(acc[mt][2 * p + 1], Ah[mt], &Bv[p][2]);
                }
        }
    }

    // epilogue: partial logits over this u-slice
    float* red = (float*)(smem + OFF_RED);
    #pragma unroll
    for (int mt = 0; mt < 2; mt++)
        #pragma unroll
        for (int hf = 0; hf < 2; hf++) {
            float p = 0.f;
            #pragma unroll
            for (int nt = 0; nt < 8; nt++) {
                int u = warp_n * 64 + nt * 8 + (lane & 3) * 2;
                p += tanh_fast(acc[mt][nt][hf * 2 + 0] + gs[u])     * vsm[u];
                p += tanh_fast(acc[mt][nt][hf * 2 + 1] + gs[u + 1]) * vsm[u + 1];
            }
            int ml = warp_m * 32 + mt * 16 + hf * 8 + (lane >> 2);
            red[ml * 9 + warp_n * 4 + (lane & 3)] = p;
        }
    __syncthreads();
    if (tid < 128) {
        float s = 0.f;
        #pragma unroll
        for (int i = 0; i < 8; i++) s += red[tid * 9 + i];
        g_lpart[us][m0 + tid] = s;
    }
}

// ---------------------------------------------------------------------------
// k_softmax: sum u-slice partials, softmax over T
// ---------------------------------------------------------------------------
__global__ __launch_bounds__(256) void k_softmax(float* __restrict__ out_w)
{
    int b = blockIdx.x, tid = threadIdx.x;
    __shared__ float smax[8], ssum[8];
    float v[8];
    float mx = -1e30f;
    #pragma unroll
    for (int i = 0; i < 8; i++) {
        int idx = b * TT + tid + i * 256;
        v[i] = g_lpart[0][idx] + g_lpart[1][idx] + g_lpart[2][idx] + g_lpart[3][idx];
        mx = fmaxf(mx, v[i]);
    }
    #pragma unroll
    for (int o = 16; o > 0; o >>= 1) mx = fmaxf(mx, __shfl_xor_sync(~0u, mx, o));
    if ((tid & 31) == 0) smax[tid >> 5] = mx;
    __syncthreads();
    mx = smax[0];
    #pragma unroll
    for (int i = 1; i < 8; i++) mx = fmaxf(mx, smax[i]);
    float s = 0.f;
    #pragma unroll
    for (int i = 0; i < 8; i++) { v[i] = expf(v[i] - mx); s += v[i]; }
    #pragma unroll
    for (int o = 16; o > 0; o >>= 1) s += __shfl_xor_sync(~0u, s, o);
    if ((tid & 31) == 0) ssum[tid >> 5] = s;
    __syncthreads();
    s = ssum[0];
    #pragma unroll
    for (int i = 1; i < 8; i++) s += ssum[i];
    float inv = 1.f / s;
    #pragma unroll
    for (int i = 0; i < 8; i++) out_w[b * TT + tid + i * 256] = v[i] * inv;
}

// ---------------------------------------------------------------------------
// k_ctx_part / k_ctx_red: context = sum_t w * F, two-stage deterministic
// ---------------------------------------------------------------------------
__global__ __launch_bounds__(256) void k_ctx_part(
    const float* __restrict__ F, const float* __restrict__ w)
{
    int tc = blockIdx.x, b = blockIdx.y, tid = threadIdx.x;
    __shared__ float ws[64];
    if (tid < 64) ws[tid] = w[b * TT + tc * 64 + tid];
    __syncthreads();
    int q = tid & 127, r2 = tid >> 7;
    const float4* F4 = (const float4*)(F + ((size_t)b * TT + (size_t)tc * 64) * DD) + q;
    float ax = 0.f, ay = 0.f, az = 0.f, aw = 0.f;
    #pragma unroll 8
    for (int i = 0; i < 32; i++) {
        int t = r2 + 2 * i;
        float wv = ws[t];
        float4 v = F4[(size_t)t * 128];
        ax = fmaf(wv, v.x, ax); ay = fmaf(wv, v.y, ay);
        az = fmaf(wv, v.z, az); aw = fmaf(wv, v.w, aw);
    }
    float4 o; o.x = ax; o.y = ay; o.z = az; o.w = aw;
    ((float4*)&g_part[b][tc][r2][0])[q] = o;
}

__global__ __launch_bounds__(512) void k_ctx_red(float* __restrict__ out_c)
{
    int b = blockIdx.x, d = threadIdx.x;
    float s = 0.f;
    const float* p = &g_part[b][0][0][0];
    #pragma unroll
    for (int i = 0; i < 64; i++) s += p[i * DD + d];
    out_c[b * DD + d] = s;
}

// ---------------------------------------------------------------------------
extern "C" void kernel_launch(void* const* d_in, const int* in_sizes, int n_in,
                              void* d_out, int out_size)
{
    const float* features = (const float*)d_in[0];
    const float* hidden   = (const float*)d_in[1];
    const float* W1_w     = (const float*)d_in[2];
    const float* W1_b     = (const float*)d_in[3];
    const float* W2_w     = (const float*)d_in[4];
    const float* W2_b     = (const float*)d_in[5];
    const float* V_w      = (const float*)d_in[6];
    // V_b cancels in softmax

    float* out   = (float*)d_out;
    float* out_c = out;               // [B, D]
    float* out_w = out + BB * DD;     // [B, T, 1]

    cudaFuncSetAttribute(k_logits, cudaFuncAttributeMaxDynamicSharedMemorySize, SMEM_BYTES);

    k_prep   <<<576, 512>>>(W1_w, hidden, W2_w, W2_b, W1_b);
    k_logits <<<dim3(4, 1024), 256, SMEM_BYTES>>>(features, V_w);
    k_softmax<<<BB, 256>>>(out_w);
    k_ctx_part<<<dim3(32, BB), 256>>>(features, out_w);
    k_ctx_red<<<BB, 512>>>(out_c);
}